// round 14
// baseline (speedup 1.0000x reference)
#include <cuda_runtime.h>

#define LAM 0.95f
#define ETA 0.5f
#define B_SZ 128
#define D_SZ 1024
#define VEC_PER_ROW (D_SZ / 4)   // 256
#define ROWS_PER_BLK 4

// out[b,i,j] = LAM*A[b,i,j] + ETA*h[b,i]*h[b,j]
//
// FINAL kernel. Converged optimum, 156.128 us wall reproduced in three
// independent rounds (DRAM ~86%, 6.82-6.86 TB/s sustained = the mixed-stream
// HBM3e ceiling on sm_103a). Structure:
//   - one block = 4 consecutive rows of one batch; 256 threads; thread t owns
//     column-group j4 = t for all 4 rows (hj loaded once; h is L2-resident)
//   - read phase: 4 front-batched streaming loads (MLP=4, .cs)
//   - compute in place (regs stay 32, occ ~82%)
//   - write phase: 4 back-to-back streaming stores (.cs)
//   - 32768 independent blocks
// All SM pipes <11% busy; the kernel is HBM read/write-turnaround bound.
// Tested and neutral/worse: MLP=8, 2x4 row grouping, st.wt, default-cached
// loads, 256-bit v8 accesses, 128-thread blocks, 2D grid.
__global__ void __launch_bounds__(256) fastweight_kernel(
    const float4* __restrict__ A,
    const float* __restrict__ h,
    float4* __restrict__ out)
{
    int blk = blockIdx.x;
    int b  = blk >> 8;                    // 256 row-groups per batch (1024/4)
    int rg = blk & 255;
    int i0 = rg * ROWS_PER_BLK;
    int t  = threadIdx.x;                 // j4 in [0,256)

    int base = (b * D_SZ + i0) * VEC_PER_ROW + t;   // fits in 32 bits

    const float4 hj = __ldg(((const float4*)h) + b * VEC_PER_ROW + t);

    const float* hrow = h + b * D_SZ + i0;
    float hi0 = __ldg(hrow + 0) * ETA;
    float hi1 = __ldg(hrow + 1) * ETA;
    float hi2 = __ldg(hrow + 2) * ETA;
    float hi3 = __ldg(hrow + 3) * ETA;

    // Read phase: 4 front-batched streaming loads (MLP=4)
    float4 a0 = __ldcs(A + base + 0 * VEC_PER_ROW);
    float4 a1 = __ldcs(A + base + 1 * VEC_PER_ROW);
    float4 a2 = __ldcs(A + base + 2 * VEC_PER_ROW);
    float4 a3 = __ldcs(A + base + 3 * VEC_PER_ROW);

    // Compute phase: results in place, registers stay at 32
    a0.x = fmaf(hi0, hj.x, a0.x * LAM);
    a0.y = fmaf(hi0, hj.y, a0.y * LAM);
    a0.z = fmaf(hi0, hj.z, a0.z * LAM);
    a0.w = fmaf(hi0, hj.w, a0.w * LAM);

    a1.x = fmaf(hi1, hj.x, a1.x * LAM);
    a1.y = fmaf(hi1, hj.y, a1.y * LAM);
    a1.z = fmaf(hi1, hj.z, a1.z * LAM);
    a1.w = fmaf(hi1, hj.w, a1.w * LAM);

    a2.x = fmaf(hi2, hj.x, a2.x * LAM);
    a2.y = fmaf(hi2, hj.y, a2.y * LAM);
    a2.z = fmaf(hi2, hj.z, a2.z * LAM);
    a2.w = fmaf(hi2, hj.w, a2.w * LAM);

    a3.x = fmaf(hi3, hj.x, a3.x * LAM);
    a3.y = fmaf(hi3, hj.y, a3.y * LAM);
    a3.z = fmaf(hi3, hj.z, a3.z * LAM);
    a3.w = fmaf(hi3, hj.w, a3.w * LAM);

    // Write phase: 4 back-to-back streaming stores
    __stcs(out + base + 0 * VEC_PER_ROW, a0);
    __stcs(out + base + 1 * VEC_PER_ROW, a1);
    __stcs(out + base + 2 * VEC_PER_ROW, a2);
    __stcs(out + base + 3 * VEC_PER_ROW, a3);
}

extern "C" void kernel_launch(void* const* d_in, const int* in_sizes, int n_in,
                              void* d_out, int out_size) {
    const float4* A = (const float4*)d_in[0];
    const float*  h = (const float*)d_in[1];
    float4* out = (float4*)d_out;

    // grid = B * (D / 4) = 128 * 256 = 32768 blocks
    int blocks = B_SZ * (D_SZ / ROWS_PER_BLK);
    fastweight_kernel<<<blocks, 256>>>(A, h, out);
}

// round 15
// speedup vs baseline: 1.0004x; 1.0004x over previous
#include <cuda_runtime.h>

#define LAM 0.95f
#define ETA 0.5f
#define B_SZ 128
#define D_SZ 1024
#define VEC_PER_ROW (D_SZ / 4)   // 256
#define ROWS_PER_BLK 4

// out[b,i,j] = LAM*A[b,i,j] + ETA*h[b,i]*h[b,j]
//
// FINAL kernel. Converged optimum: 156.1-156.2 us wall across six
// measurements (DRAM 85-86.5%, 6.83-6.86 TB/s sustained = the mixed-stream
// HBM3e turnaround ceiling on sm_103a). Structure:
//   - one block = 4 consecutive rows of one batch; 256 threads; thread t owns
//     column-group j4 = t for all 4 rows (hj loaded once; h is L2-resident)
//   - read phase: 4 front-batched streaming loads (MLP=4, .cs)
//   - compute in place (regs 32, occ ~81%)
//   - write phase: 4 back-to-back streaming stores (.cs)
//   - 32768 independent blocks
// All SM pipes <11% busy. Tested and neutral/worse across the session:
// MLP=8, 2x4 row grouping, st.wt, default-cached loads, 256-bit v8 accesses,
// 128-thread blocks, 2D grid, interleaved store scheduling.
__global__ void __launch_bounds__(256) fastweight_kernel(
    const float4* __restrict__ A,
    const float* __restrict__ h,
    float4* __restrict__ out)
{
    int blk = blockIdx.x;
    int b  = blk >> 8;                    // 256 row-groups per batch (1024/4)
    int rg = blk & 255;
    int i0 = rg * ROWS_PER_BLK;
    int t  = threadIdx.x;                 // j4 in [0,256)

    int base = (b * D_SZ + i0) * VEC_PER_ROW + t;   // fits in 32 bits

    const float4 hj = __ldg(((const float4*)h) + b * VEC_PER_ROW + t);

    const float* hrow = h + b * D_SZ + i0;
    float hi0 = __ldg(hrow + 0) * ETA;
    float hi1 = __ldg(hrow + 1) * ETA;
    float hi2 = __ldg(hrow + 2) * ETA;
    float hi3 = __ldg(hrow + 3) * ETA;

    // Read phase: 4 front-batched streaming loads (MLP=4)
    float4 a0 = __ldcs(A + base + 0 * VEC_PER_ROW);
    float4 a1 = __ldcs(A + base + 1 * VEC_PER_ROW);
    float4 a2 = __ldcs(A + base + 2 * VEC_PER_ROW);
    float4 a3 = __ldcs(A + base + 3 * VEC_PER_ROW);

    // Compute phase: results in place, registers stay at 32
    a0.x = fmaf(hi0, hj.x, a0.x * LAM);
    a0.y = fmaf(hi0, hj.y, a0.y * LAM);
    a0.z = fmaf(hi0, hj.z, a0.z * LAM);
    a0.w = fmaf(hi0, hj.w, a0.w * LAM);

    a1.x = fmaf(hi1, hj.x, a1.x * LAM);
    a1.y = fmaf(hi1, hj.y, a1.y * LAM);
    a1.z = fmaf(hi1, hj.z, a1.z * LAM);
    a1.w = fmaf(hi1, hj.w, a1.w * LAM);

    a2.x = fmaf(hi2, hj.x, a2.x * LAM);
    a2.y = fmaf(hi2, hj.y, a2.y * LAM);
    a2.z = fmaf(hi2, hj.z, a2.z * LAM);
    a2.w = fmaf(hi2, hj.w, a2.w * LAM);

    a3.x = fmaf(hi3, hj.x, a3.x * LAM);
    a3.y = fmaf(hi3, hj.y, a3.y * LAM);
    a3.z = fmaf(hi3, hj.z, a3.z * LAM);
    a3.w = fmaf(hi3, hj.w, a3.w * LAM);

    // Write phase: 4 back-to-back streaming stores
    __stcs(out + base + 0 * VEC_PER_ROW, a0);
    __stcs(out + base + 1 * VEC_PER_ROW, a1);
    __stcs(out + base + 2 * VEC_PER_ROW, a2);
    __stcs(out + base + 3 * VEC_PER_ROW, a3);
}

extern "C" void kernel_launch(void* const* d_in, const int* in_sizes, int n_in,
                              void* d_out, int out_size) {
    const float4* A = (const float4*)d_in[0];
    const float*  h = (const float*)d_in[1];
    float4* out = (float4*)d_out;

    // grid = B * (D / 4) = 128 * 256 = 32768 blocks
    int blocks = B_SZ * (D_SZ / ROWS_PER_BLK);
    fastweight_kernel<<<blocks, 256>>>(A, h, out);
}